// round 14
// baseline (speedup 1.0000x reference)
#include <cuda_runtime.h>
#include <cuda_fp16.h>
#include <cstdint>
#include <cstddef>

#define S_LEN 2048
#define BATCH 4
#define DIM   1024
#define MQKV  (BATCH * S_LEN)   // 8192

// ---------------------------------------------------------------------------
// scratch (static device globals; no allocation in kernel_launch)
// ---------------------------------------------------------------------------
#define DEVH(name, n) __device__ __align__(256) __half name[n]
DEVH(g_xh,  (size_t)MQKV * DIM);
DEVH(g_wqh, (size_t)DIM * DIM);
DEVH(g_wkh, (size_t)DIM * DIM);
DEVH(g_wvh, (size_t)DIM * DIM);
DEVH(g_qh,  (size_t)MQKV * DIM);
DEVH(g_kh,  (size_t)MQKV * DIM);
DEVH(g_vh,  (size_t)MQKV * DIM);
DEVH(g_ph,  (size_t)BATCH * S_LEN * S_LEN);
__device__ __align__(256) float g_sc[(size_t)BATCH * S_LEN * S_LEN];

// ---------------------------------------------------------------------------
// PTX helpers — non-'a'-suffix ISA only (cp.async, ldmatrix, mma.sync).
// ---------------------------------------------------------------------------
__device__ __forceinline__ uint32_t smem_to_u32(const void* p) {
    uint32_t a;
    asm("{ .reg .u64 t; cvta.to.shared.u64 t, %1; cvt.u32.u64 %0, t; }"
        : "=r"(a) : "l"(p));
    return a;
}
__device__ __forceinline__ void cp_async16(uint32_t s, const void* g) {
    asm volatile("cp.async.cg.shared.global [%0], [%1], 16;" :: "r"(s), "l"(g));
}
#define CP_COMMIT() asm volatile("cp.async.commit_group;" ::: "memory")
#define CP_WAIT(n)  asm volatile("cp.async.wait_group %0;" :: "n"(n) : "memory")

__device__ __forceinline__ void ldsm_x4(uint32_t* r, uint32_t addr) {
    asm volatile("ldmatrix.sync.aligned.m8n8.x4.shared.b16 {%0,%1,%2,%3}, [%4];"
        : "=r"(r[0]), "=r"(r[1]), "=r"(r[2]), "=r"(r[3]) : "r"(addr));
}
__device__ __forceinline__ void ldsm_x4_t(uint32_t* r, uint32_t addr) {
    asm volatile("ldmatrix.sync.aligned.m8n8.x4.trans.shared.b16 {%0,%1,%2,%3}, [%4];"
        : "=r"(r[0]), "=r"(r[1]), "=r"(r[2]), "=r"(r[3]) : "r"(addr));
}
__device__ __forceinline__ void mma16816(float* c, const uint32_t* a,
                                         uint32_t b0, uint32_t b1) {
    asm volatile(
        "mma.sync.aligned.m16n8k16.row.col.f32.f16.f16.f32 "
        "{%0,%1,%2,%3}, {%4,%5,%6,%7}, {%8,%9}, {%0,%1,%2,%3};"
        : "+f"(c[0]), "+f"(c[1]), "+f"(c[2]), "+f"(c[3])
        : "r"(a[0]), "r"(a[1]), "r"(a[2]), "r"(a[3]), "r"(b0), "r"(b1));
}

// fast exp on the FMA pipe (no MUFU): exp(x) = 2^(x*log2e), deg-5 poly on
// [-0.5,0.5], exponent applied via bit trick. rel err ~2e-6. x <= 0 here.
__device__ __forceinline__ float fexp(float x) {
    float t = fmaxf(x * 1.4426950408889634f, -126.0f);
    float n = rintf(t);
    float f = t - n;
    float p = 1.3333558146428443e-3f;
    p = fmaf(p, f, 9.6181291076284772e-3f);
    p = fmaf(p, f, 5.5504108664821580e-2f);
    p = fmaf(p, f, 2.4022650695910072e-1f);
    p = fmaf(p, f, 6.9314718055994531e-1f);
    p = fmaf(p, f, 1.0f);
    uint32_t sc = (uint32_t)((int)n + 127) << 23;
    return __uint_as_float(sc) * p;
}

// up to 3 operand/output sets, selected by blockIdx.z when zsel=1
struct G3 {
    const __half* Bh[3];
    const float*  bias[3];
    float*        Cf[3];
    __half*       Ch[3];
};

// ---------------------------------------------------------------------------
// fp16 GEMM (fp32 accumulate) on tensor cores.
//   TRANSB=0: C[m,n] = sum_k A[m,k] * B[n,k]   (NT; B row-major [n,k])
//   TRANSB=1: C[m,n] = sum_k A[m,k] * B[k,n]   (NN via ldmatrix.trans)
// CTA tile 128x128, 128 threads, 4 warps (2x2) of 64x64 warp tiles,
// K-chunk 64, cp.async double buffer, 2 CTAs/SM.
// ---------------------------------------------------------------------------
#define ROW_A     144                // 64 fp16 = 128B data + 16B pad
#define TILE_A    (128 * ROW_A)      // 18432 B
#define ROW_BT    272                // 128 fp16 = 256B data + 16B pad (trans B)
#define STAGE_B2  (2 * TILE_A)       // A tile + B tile slot (36864 B)
#define GEMM_SMEM (2 * STAGE_B2)     // 73728 B

template <int TRANSB>
__global__ __launch_bounds__(128, 2)
void gemm_fp16(const __half* __restrict__ Ah,
               const G3 args,
               int M, int N, int K, float alpha,
               size_t sA, size_t sB, size_t sC, int zsel)
{
    extern __shared__ __align__(16) char smem[];
    const uint32_t smem_u = smem_to_u32(smem);

    const int tid  = threadIdx.x;
    const int wid  = tid >> 5, lane = tid & 31;
    const int wm   = wid >> 1;        // 0..1 : warp row (64 rows)
    const int wn   = wid & 1;         // 0..1 : warp col (64 cols)
    const int m0   = blockIdx.y * 128;
    const int n0   = blockIdx.x * 128;

    const int    zs = zsel ? (int)blockIdx.z : 0;
    const size_t zb = zsel ? 0 : (size_t)blockIdx.z;

    Ah += sA * zb;
    const __half* Bh = args.Bh[zs] + sB * zb;
    const float*  bias = args.bias[zs];
    float*        Cf = args.Cf[zs];
    __half*       Ch = args.Ch[zs];
    const size_t  co = sC * zb;

    // ---- loader: 1024 16B-chunks per tile, 8 per thread per tile ----
    auto load_stage = [&](int c, int s) {
        const int k0 = c * 64;
        const uint32_t st = smem_u + s * STAGE_B2;
        #pragma unroll
        for (int h = 0; h < 8; ++h) {
            int ci = tid + h * 128;
            {   // A: 128 rows x 8 chunks (128B data per row)
                int row = ci >> 3, col = ci & 7;
                cp_async16(st + row * ROW_A + col * 16,
                           Ah + (size_t)(m0 + row) * K + k0 + col * 8);
            }
            if (TRANSB == 0) {   // B row-major [n,k]: 128 rows x 8 chunks
                int row = ci >> 3, col = ci & 7;
                cp_async16(st + TILE_A + row * ROW_A + col * 16,
                           Bh + (size_t)(n0 + row) * K + k0 + col * 8);
            } else {             // B row-major [k,n]: 64 rows x 16 chunks (256B)
                int row = ci >> 4, col = ci & 15;
                cp_async16(st + TILE_A + row * ROW_BT + col * 16,
                           Bh + (size_t)(k0 + row) * N + n0 + col * 8);
            }
        }
        CP_COMMIT();
    };

    float acc[4][8][4];
    #pragma unroll
    for (int i = 0; i < 4; ++i)
        #pragma unroll
        for (int j = 0; j < 8; ++j)
            #pragma unroll
            for (int e = 0; e < 4; ++e) acc[i][j][e] = 0.f;

    const int NC = K >> 6;             // K / 64
    load_stage(0, 0);

    const uint32_t aoff = (uint32_t)((wm * 64 + (lane & 15)) * ROW_A +
                                     ((lane & 16) ? 16 : 0));
    const uint32_t boff_nt = (uint32_t)((wn * 64 + ((lane & 16) >> 1) + (lane & 7)) * ROW_A +
                                        ((lane & 8) ? 16 : 0));
    const uint32_t boff_t = (uint32_t)((((lane >> 3) & 1) * 8 + (lane & 7)) * ROW_BT +
                                       (wn * 64 + (lane >> 4) * 8) * 2);

    for (int c = 0; c < NC; ++c) {
        if (c + 1 < NC) { load_stage(c + 1, (c + 1) & 1); CP_WAIT(1); }
        else            { CP_WAIT(0); }
        __syncthreads();

        const uint32_t st = smem_u + (c & 1) * STAGE_B2;
        #pragma unroll
        for (int kk = 0; kk < 4; ++kk) {    // four k16 steps per chunk
            uint32_t bhf[4][4];
            if (TRANSB == 0) {
                const uint32_t kb = kk * 32;            // 16 fp16 = 32 B
                #pragma unroll
                for (int j = 0; j < 4; ++j)
                    ldsm_x4(bhf[j], st + TILE_A + boff_nt + kb + j * (16 * ROW_A));
            } else {
                const uint32_t kb = kk * 16 * ROW_BT;   // 16 k-rows down
                #pragma unroll
                for (int j = 0; j < 4; ++j)
                    ldsm_x4_t(bhf[j], st + TILE_A + boff_t + kb + j * 32);
            }
            #pragma unroll
            for (int mi = 0; mi < 4; ++mi) {
                uint32_t ahf[4];
                ldsm_x4(ahf, st + aoff + kk * 32 + mi * (16 * ROW_A));
                #pragma unroll
                for (int nf = 0; nf < 8; ++nf) {
                    const int j = nf >> 1, p = (nf & 1) * 2;
                    mma16816(acc[mi][nf], ahf, bhf[j][p], bhf[j][p + 1]);
                }
            }
        }
        __syncthreads();
    }

    // ---- epilogue ----
    const int r0 = lane >> 2;
    const int c0l = (lane & 3) * 2;
    #pragma unroll
    for (int mi = 0; mi < 4; ++mi) {
        #pragma unroll
        for (int nf = 0; nf < 8; ++nf) {
            const int col  = n0 + wn * 64 + nf * 8 + c0l;
            const int rowA = m0 + wm * 64 + mi * 16 + r0;
            float b0 = 0.f, b1 = 0.f;
            if (bias) { b0 = bias[col]; b1 = bias[col + 1]; }
            float v0 = fmaf(alpha, acc[mi][nf][0], b0);
            float v1 = fmaf(alpha, acc[mi][nf][1], b1);
            float v2 = fmaf(alpha, acc[mi][nf][2], b0);
            float v3 = fmaf(alpha, acc[mi][nf][3], b1);
            if (Cf) {
                float* p0 = Cf + co + (size_t)rowA * N + col;
                *(float2*)p0                     = make_float2(v0, v1);
                *(float2*)(p0 + (size_t)8 * N)   = make_float2(v2, v3);
            }
            if (Ch) {
                size_t o0 = co + (size_t)rowA * N + col;
                *(__half2*)(Ch + o0) =
                    __halves2half2(__float2half_rn(v0), __float2half_rn(v1));
                *(__half2*)(Ch + o0 + (size_t)8 * N) =
                    __halves2half2(__float2half_rn(v2), __float2half_rn(v3));
            }
        }
    }
}

// ---------------------------------------------------------------------------
// x (S,B,D) fp32 -> xf (B,S,D) fp16
// ---------------------------------------------------------------------------
__global__ __launch_bounds__(256) void conv_x(const float* __restrict__ x,
                                              __half* __restrict__ xh) {
    int bs = blockIdx.x;
    int b = bs / S_LEN, s = bs % S_LEN;
    float4 v = ((const float4*)(x + ((size_t)s * BATCH + b) * DIM))[threadIdx.x];
    size_t o = (size_t)bs * DIM + (size_t)threadIdx.x * 4;
    ((__half2*)(xh + o))[0] = __halves2half2(__float2half_rn(v.x),
                                             __float2half_rn(v.y));
    ((__half2*)(xh + o))[1] = __halves2half2(__float2half_rn(v.z),
                                             __float2half_rn(v.w));
}

// 3 fp32 arrays -> fp16, z-indexed (one launch for Wq, Wk, Wv)
struct C3 { const float* X[3]; __half* H[3]; };
__global__ __launch_bounds__(256) void conv_hi3(const C3 a, int n4) {
    int i = blockIdx.x * 256 + threadIdx.x;
    if (i >= n4) return;
    const int z = blockIdx.z;
    float4 v = ((const float4*)a.X[z])[i];
    size_t o = (size_t)i * 4;
    ((__half2*)(a.H[z] + o))[0] = __halves2half2(__float2half_rn(v.x),
                                                 __float2half_rn(v.y));
    ((__half2*)(a.H[z] + o))[1] = __halves2half2(__float2half_rn(v.z),
                                                 __float2half_rn(v.w));
}

// softmax over rows of sc (fp32, len S_LEN) -> fp16 probs.
// exp via FMA-pipe polynomial (fexp) — the MUFU path was the bottleneck
// (16.8M EX2 at rt8/SMSP ~= 113us chip-time).
__global__ __launch_bounds__(256) void softmax_conv(const float* __restrict__ sc,
                                                    __half* __restrict__ ph) {
    const int tid = threadIdx.x;
    const float4* p4 = (const float4*)(sc + (size_t)blockIdx.x * S_LEN);
    __shared__ float red[8];

    float4 a = p4[tid], b = p4[tid + 256];
    float lmax = fmaxf(fmaxf(fmaxf(a.x, a.y), fmaxf(a.z, a.w)),
                       fmaxf(fmaxf(b.x, b.y), fmaxf(b.z, b.w)));
    #pragma unroll
    for (int o = 16; o; o >>= 1) lmax = fmaxf(lmax, __shfl_xor_sync(~0u, lmax, o));
    if ((tid & 31) == 0) red[tid >> 5] = lmax;
    __syncthreads();
    float gmax = red[0];
    #pragma unroll
    for (int w = 1; w < 8; ++w) gmax = fmaxf(gmax, red[w]);
    __syncthreads();

    float e[8];
    e[0] = fexp(a.x - gmax); e[1] = fexp(a.y - gmax);
    e[2] = fexp(a.z - gmax); e[3] = fexp(a.w - gmax);
    e[4] = fexp(b.x - gmax); e[5] = fexp(b.y - gmax);
    e[6] = fexp(b.z - gmax); e[7] = fexp(b.w - gmax);
    float lsum = ((e[0]+e[1]) + (e[2]+e[3])) + ((e[4]+e[5]) + (e[6]+e[7]));
    #pragma unroll
    for (int o = 16; o; o >>= 1) lsum += __shfl_xor_sync(~0u, lsum, o);
    if ((tid & 31) == 0) red[tid >> 5] = lsum;
    __syncthreads();
    float gsum = 0.f;
    #pragma unroll
    for (int w = 0; w < 8; ++w) gsum += red[w];
    float inv = 1.f / gsum;

    size_t o0 = (size_t)blockIdx.x * S_LEN + (size_t)tid * 4;
    #pragma unroll
    for (int half = 0; half < 2; ++half) {
        size_t o = o0 + half * 1024;
        ((__half2*)(ph + o))[0] = __halves2half2(__float2half_rn(e[half*4+0] * inv),
                                                 __float2half_rn(e[half*4+1] * inv));
        ((__half2*)(ph + o))[1] = __halves2half2(__float2half_rn(e[half*4+2] * inv),
                                                 __float2half_rn(e[half*4+3] * inv));
    }
}

// ---------------------------------------------------------------------------
extern "C" void kernel_launch(void* const* d_in, const int* in_sizes, int n_in,
                              void* d_out, int out_size) {
    const float* x  = (const float*)d_in[0];
    const float* Wq = (const float*)d_in[1];
    const float* bq = (const float*)d_in[2];
    const float* Wk = (const float*)d_in[3];
    const float* bk = (const float*)d_in[4];
    const float* Wv = (const float*)d_in[5];
    const float* bv = (const float*)d_in[6];
    float* out = (float*)d_out;

    cudaFuncSetAttribute(gemm_fp16<0>, cudaFuncAttributeMaxDynamicSharedMemorySize,
                         GEMM_SMEM);
    cudaFuncSetAttribute(gemm_fp16<1>, cudaFuncAttributeMaxDynamicSharedMemorySize,
                         GEMM_SMEM);

    __half *xh, *wqh, *wkh, *wvh, *qh, *kh, *vh, *ph;
    float* sc;
    cudaGetSymbolAddress((void**)&xh, g_xh);
    cudaGetSymbolAddress((void**)&wqh, g_wqh);
    cudaGetSymbolAddress((void**)&wkh, g_wkh);
    cudaGetSymbolAddress((void**)&wvh, g_wvh);
    cudaGetSymbolAddress((void**)&qh, g_qh);
    cudaGetSymbolAddress((void**)&kh, g_kh);
    cudaGetSymbolAddress((void**)&vh, g_vh);
    cudaGetSymbolAddress((void**)&ph, g_ph);
    cudaGetSymbolAddress((void**)&sc, g_sc);

    // 1) input conversions
    conv_x<<<MQKV, 256>>>(x, xh);
    {
        C3 c{};
        c.X[0] = Wq; c.X[1] = Wk; c.X[2] = Wv;
        c.H[0] = wqh; c.H[1] = wkh; c.H[2] = wvh;
        dim3 grid(DIM * DIM / 4 / 256, 1, 3);
        conv_hi3<<<grid, 256>>>(c, DIM * DIM / 4);
    }

    // 2) fused QKV projections (NT; one launch, z selects weight set)
    {
        G3 a{};
        a.Bh[0] = wqh; a.Bh[1] = wkh; a.Bh[2] = wvh;
        a.bias[0] = bq; a.bias[1] = bk; a.bias[2] = bv;
        a.Ch[0] = qh; a.Ch[1] = kh; a.Ch[2] = vh;
        dim3 grid(DIM / 128, MQKV / 128, 3);
        gemm_fp16<0><<<grid, 128, GEMM_SMEM>>>(xh, a,
                                               MQKV, DIM, DIM, 1.f, 0, 0, 0, 1);
    }

    // 3) scores = Q K^T / sqrt(D)  (NT)
    {
        G3 a{};
        a.Bh[0] = kh; a.Cf[0] = sc;
        dim3 grid(S_LEN / 128, S_LEN / 128, BATCH);
        gemm_fp16<0><<<grid, 128, GEMM_SMEM>>>(qh, a,
                                               S_LEN, S_LEN, DIM, 0.03125f,
                                               (size_t)S_LEN * DIM, (size_t)S_LEN * DIM,
                                               (size_t)S_LEN * S_LEN, 0);
    }

    // 4) softmax -> fp16 probs (FMA-pipe exp)
    softmax_conv<<<BATCH * S_LEN, 256>>>(sc, ph);

    // 5) out = P V  (NN via ldmatrix.trans; V used in natural [S,D] layout)
    {
        G3 a{};
        a.Bh[0] = vh; a.Cf[0] = out;
        dim3 grid(DIM / 128, S_LEN / 128, BATCH);
        gemm_fp16<1><<<grid, 128, GEMM_SMEM>>>(ph, a,
                                               S_LEN, DIM, S_LEN, 1.f,
                                               (size_t)S_LEN * S_LEN, (size_t)S_LEN * DIM,
                                               (size_t)S_LEN * DIM, 0);
    }
}

// round 15
// speedup vs baseline: 1.0074x; 1.0074x over previous
#include <cuda_runtime.h>
#include <cuda_fp16.h>
#include <cstdint>
#include <cstddef>

#define S_LEN 2048
#define BATCH 4
#define DIM   1024
#define MQKV  (BATCH * S_LEN)   // 8192

// ---------------------------------------------------------------------------
// scratch (static device globals; no allocation in kernel_launch)
// ---------------------------------------------------------------------------
#define DEVH(name, n) __device__ __align__(256) __half name[n]
DEVH(g_xh,  (size_t)MQKV * DIM);
DEVH(g_wqh, (size_t)DIM * DIM);
DEVH(g_wkh, (size_t)DIM * DIM);
DEVH(g_wvh, (size_t)DIM * DIM);
DEVH(g_qh,  (size_t)MQKV * DIM);
DEVH(g_kh,  (size_t)MQKV * DIM);
DEVH(g_vh,  (size_t)MQKV * DIM);
DEVH(g_sch, (size_t)BATCH * S_LEN * S_LEN);   // scores, fp16
DEVH(g_ph,  (size_t)BATCH * S_LEN * S_LEN);   // probs, fp16

// ---------------------------------------------------------------------------
// PTX helpers — non-'a'-suffix ISA only (cp.async, ldmatrix, mma.sync).
// ---------------------------------------------------------------------------
__device__ __forceinline__ uint32_t smem_to_u32(const void* p) {
    uint32_t a;
    asm("{ .reg .u64 t; cvta.to.shared.u64 t, %1; cvt.u32.u64 %0, t; }"
        : "=r"(a) : "l"(p));
    return a;
}
__device__ __forceinline__ void cp_async16(uint32_t s, const void* g) {
    asm volatile("cp.async.cg.shared.global [%0], [%1], 16;" :: "r"(s), "l"(g));
}
#define CP_COMMIT() asm volatile("cp.async.commit_group;" ::: "memory")
#define CP_WAIT(n)  asm volatile("cp.async.wait_group %0;" :: "n"(n) : "memory")

__device__ __forceinline__ void ldsm_x4(uint32_t* r, uint32_t addr) {
    asm volatile("ldmatrix.sync.aligned.m8n8.x4.shared.b16 {%0,%1,%2,%3}, [%4];"
        : "=r"(r[0]), "=r"(r[1]), "=r"(r[2]), "=r"(r[3]) : "r"(addr));
}
__device__ __forceinline__ void ldsm_x4_t(uint32_t* r, uint32_t addr) {
    asm volatile("ldmatrix.sync.aligned.m8n8.x4.trans.shared.b16 {%0,%1,%2,%3}, [%4];"
        : "=r"(r[0]), "=r"(r[1]), "=r"(r[2]), "=r"(r[3]) : "r"(addr));
}
__device__ __forceinline__ void mma16816(float* c, const uint32_t* a,
                                         uint32_t b0, uint32_t b1) {
    asm volatile(
        "mma.sync.aligned.m16n8k16.row.col.f32.f16.f16.f32 "
        "{%0,%1,%2,%3}, {%4,%5,%6,%7}, {%8,%9}, {%0,%1,%2,%3};"
        : "+f"(c[0]), "+f"(c[1]), "+f"(c[2]), "+f"(c[3])
        : "r"(a[0]), "r"(a[1]), "r"(a[2]), "r"(a[3]), "r"(b0), "r"(b1));
}

// fast exp on the FMA pipe (no MUFU): exp(x) = 2^(x*log2e), deg-5 poly.
__device__ __forceinline__ float fexp(float x) {
    float t = fmaxf(x * 1.4426950408889634f, -126.0f);
    float n = rintf(t);
    float f = t - n;
    float p = 1.3333558146428443e-3f;
    p = fmaf(p, f, 9.6181291076284772e-3f);
    p = fmaf(p, f, 5.5504108664821580e-2f);
    p = fmaf(p, f, 2.4022650695910072e-1f);
    p = fmaf(p, f, 6.9314718055994531e-1f);
    p = fmaf(p, f, 1.0f);
    uint32_t sc = (uint32_t)((int)n + 127) << 23;
    return __uint_as_float(sc) * p;
}

// up to 3 operand/output sets, selected by blockIdx.z when zsel=1
struct G3 {
    const __half* Bh[3];
    const float*  bias[3];
    float*        Cf[3];
    __half*       Ch[3];
};

// ---------------------------------------------------------------------------
// fp16 GEMM (fp32 accumulate) on tensor cores.
//   TRANSB=0: C[m,n] = sum_k A[m,k] * B[n,k]   (NT; B row-major [n,k])
//   TRANSB=1: C[m,n] = sum_k A[m,k] * B[k,n]   (NN via ldmatrix.trans)
// CTA tile 128x128, 128 threads, 4 warps (2x2) of 64x64 warp tiles,
// K-chunk 64, cp.async double buffer, 2 CTAs/SM.
// ---------------------------------------------------------------------------
#define ROW_A     144                // 64 fp16 = 128B data + 16B pad
#define TILE_A    (128 * ROW_A)      // 18432 B
#define ROW_BT    272                // 128 fp16 = 256B data + 16B pad (trans B)
#define STAGE_B2  (2 * TILE_A)       // A tile + B tile slot (36864 B)
#define GEMM_SMEM (2 * STAGE_B2)     // 73728 B

template <int TRANSB>
__global__ __launch_bounds__(128, 2)
void gemm_fp16(const __half* __restrict__ Ah,
               const G3 args,
               int M, int N, int K, float alpha,
               size_t sA, size_t sB, size_t sC, int zsel)
{
    extern __shared__ __align__(16) char smem[];
    const uint32_t smem_u = smem_to_u32(smem);

    const int tid  = threadIdx.x;
    const int wid  = tid >> 5, lane = tid & 31;
    const int wm   = wid >> 1;        // 0..1 : warp row (64 rows)
    const int wn   = wid & 1;         // 0..1 : warp col (64 cols)
    const int m0   = blockIdx.y * 128;
    const int n0   = blockIdx.x * 128;

    const int    zs = zsel ? (int)blockIdx.z : 0;
    const size_t zb = zsel ? 0 : (size_t)blockIdx.z;

    Ah += sA * zb;
    const __half* Bh = args.Bh[zs] + sB * zb;
    const float*  bias = args.bias[zs];
    float*        Cf = args.Cf[zs];
    __half*       Ch = args.Ch[zs];
    const size_t  co = sC * zb;

    // ---- loader: 1024 16B-chunks per tile, 8 per thread per tile ----
    auto load_stage = [&](int c, int s) {
        const int k0 = c * 64;
        const uint32_t st = smem_u + s * STAGE_B2;
        #pragma unroll
        for (int h = 0; h < 8; ++h) {
            int ci = tid + h * 128;
            {   // A: 128 rows x 8 chunks (128B data per row)
                int row = ci >> 3, col = ci & 7;
                cp_async16(st + row * ROW_A + col * 16,
                           Ah + (size_t)(m0 + row) * K + k0 + col * 8);
            }
            if (TRANSB == 0) {   // B row-major [n,k]: 128 rows x 8 chunks
                int row = ci >> 3, col = ci & 7;
                cp_async16(st + TILE_A + row * ROW_A + col * 16,
                           Bh + (size_t)(n0 + row) * K + k0 + col * 8);
            } else {             // B row-major [k,n]: 64 rows x 16 chunks (256B)
                int row = ci >> 4, col = ci & 15;
                cp_async16(st + TILE_A + row * ROW_BT + col * 16,
                           Bh + (size_t)(k0 + row) * N + n0 + col * 8);
            }
        }
        CP_COMMIT();
    };

    float acc[4][8][4];
    #pragma unroll
    for (int i = 0; i < 4; ++i)
        #pragma unroll
        for (int j = 0; j < 8; ++j)
            #pragma unroll
            for (int e = 0; e < 4; ++e) acc[i][j][e] = 0.f;

    const int NC = K >> 6;             // K / 64
    load_stage(0, 0);

    const uint32_t aoff = (uint32_t)((wm * 64 + (lane & 15)) * ROW_A +
                                     ((lane & 16) ? 16 : 0));
    const uint32_t boff_nt = (uint32_t)((wn * 64 + ((lane & 16) >> 1) + (lane & 7)) * ROW_A +
                                        ((lane & 8) ? 16 : 0));
    const uint32_t boff_t = (uint32_t)((((lane >> 3) & 1) * 8 + (lane & 7)) * ROW_BT +
                                       (wn * 64 + (lane >> 4) * 8) * 2);

    for (int c = 0; c < NC; ++c) {
        if (c + 1 < NC) { load_stage(c + 1, (c + 1) & 1); CP_WAIT(1); }
        else            { CP_WAIT(0); }
        __syncthreads();

        const uint32_t st = smem_u + (c & 1) * STAGE_B2;
        #pragma unroll
        for (int kk = 0; kk < 4; ++kk) {    // four k16 steps per chunk
            uint32_t bhf[4][4];
            if (TRANSB == 0) {
                const uint32_t kb = kk * 32;            // 16 fp16 = 32 B
                #pragma unroll
                for (int j = 0; j < 4; ++j)
                    ldsm_x4(bhf[j], st + TILE_A + boff_nt + kb + j * (16 * ROW_A));
            } else {
                const uint32_t kb = kk * 16 * ROW_BT;   // 16 k-rows down
                #pragma unroll
                for (int j = 0; j < 4; ++j)
                    ldsm_x4_t(bhf[j], st + TILE_A + boff_t + kb + j * 32);
            }
            #pragma unroll
            for (int mi = 0; mi < 4; ++mi) {
                uint32_t ahf[4];
                ldsm_x4(ahf, st + aoff + kk * 32 + mi * (16 * ROW_A));
                #pragma unroll
                for (int nf = 0; nf < 8; ++nf) {
                    const int j = nf >> 1, p = (nf & 1) * 2;
                    mma16816(acc[mi][nf], ahf, bhf[j][p], bhf[j][p + 1]);
                }
            }
        }
        __syncthreads();
    }

    // ---- epilogue ----
    const int r0 = lane >> 2;
    const int c0l = (lane & 3) * 2;
    #pragma unroll
    for (int mi = 0; mi < 4; ++mi) {
        #pragma unroll
        for (int nf = 0; nf < 8; ++nf) {
            const int col  = n0 + wn * 64 + nf * 8 + c0l;
            const int rowA = m0 + wm * 64 + mi * 16 + r0;
            float b0 = 0.f, b1 = 0.f;
            if (bias) { b0 = bias[col]; b1 = bias[col + 1]; }
            float v0 = fmaf(alpha, acc[mi][nf][0], b0);
            float v1 = fmaf(alpha, acc[mi][nf][1], b1);
            float v2 = fmaf(alpha, acc[mi][nf][2], b0);
            float v3 = fmaf(alpha, acc[mi][nf][3], b1);
            if (Cf) {
                float* p0 = Cf + co + (size_t)rowA * N + col;
                *(float2*)p0                     = make_float2(v0, v1);
                *(float2*)(p0 + (size_t)8 * N)   = make_float2(v2, v3);
            }
            if (Ch) {
                size_t o0 = co + (size_t)rowA * N + col;
                *(__half2*)(Ch + o0) =
                    __halves2half2(__float2half_rn(v0), __float2half_rn(v1));
                *(__half2*)(Ch + o0 + (size_t)8 * N) =
                    __halves2half2(__float2half_rn(v2), __float2half_rn(v3));
            }
        }
    }
}

// ---------------------------------------------------------------------------
// x (S,B,D) fp32 -> xf (B,S,D) fp16
// ---------------------------------------------------------------------------
__global__ __launch_bounds__(256) void conv_x(const float* __restrict__ x,
                                              __half* __restrict__ xh) {
    int bs = blockIdx.x;
    int b = bs / S_LEN, s = bs % S_LEN;
    float4 v = ((const float4*)(x + ((size_t)s * BATCH + b) * DIM))[threadIdx.x];
    size_t o = (size_t)bs * DIM + (size_t)threadIdx.x * 4;
    ((__half2*)(xh + o))[0] = __halves2half2(__float2half_rn(v.x),
                                             __float2half_rn(v.y));
    ((__half2*)(xh + o))[1] = __halves2half2(__float2half_rn(v.z),
                                             __float2half_rn(v.w));
}

// 3 fp32 arrays -> fp16, z-indexed (one launch for Wq, Wk, Wv)
struct C3 { const float* X[3]; __half* H[3]; };
__global__ __launch_bounds__(256) void conv_hi3(const C3 a, int n4) {
    int i = blockIdx.x * 256 + threadIdx.x;
    if (i >= n4) return;
    const int z = blockIdx.z;
    float4 v = ((const float4*)a.X[z])[i];
    size_t o = (size_t)i * 4;
    ((__half2*)(a.H[z] + o))[0] = __halves2half2(__float2half_rn(v.x),
                                                 __float2half_rn(v.y));
    ((__half2*)(a.H[z] + o))[1] = __halves2half2(__float2half_rn(v.z),
                                                 __float2half_rn(v.w));
}

// softmax over rows of sch (fp16, len S_LEN) -> fp16 probs.
// One uint4 (8 halfs) load + one uint4 store per thread; fp32 math inside.
__global__ __launch_bounds__(256) void softmax_h(const __half* __restrict__ sch,
                                                 __half* __restrict__ ph) {
    const int tid = threadIdx.x;
    const uint4* p = (const uint4*)(sch + (size_t)blockIdx.x * S_LEN);
    __shared__ float red[8];

    uint4 r = p[tid];
    float e[8];
    {
        __half2 h0 = *(__half2*)&r.x, h1 = *(__half2*)&r.y;
        __half2 h2 = *(__half2*)&r.z, h3 = *(__half2*)&r.w;
        float2 f0 = __half22float2(h0), f1 = __half22float2(h1);
        float2 f2 = __half22float2(h2), f3 = __half22float2(h3);
        e[0] = f0.x; e[1] = f0.y; e[2] = f1.x; e[3] = f1.y;
        e[4] = f2.x; e[5] = f2.y; e[6] = f3.x; e[7] = f3.y;
    }

    float lmax = e[0];
    #pragma unroll
    for (int i = 1; i < 8; ++i) lmax = fmaxf(lmax, e[i]);
    #pragma unroll
    for (int o = 16; o; o >>= 1) lmax = fmaxf(lmax, __shfl_xor_sync(~0u, lmax, o));
    if ((tid & 31) == 0) red[tid >> 5] = lmax;
    __syncthreads();
    float gmax = red[0];
    #pragma unroll
    for (int w = 1; w < 8; ++w) gmax = fmaxf(gmax, red[w]);
    __syncthreads();

    float lsum = 0.f;
    #pragma unroll
    for (int i = 0; i < 8; ++i) { e[i] = fexp(e[i] - gmax); lsum += e[i]; }
    #pragma unroll
    for (int o = 16; o; o >>= 1) lsum += __shfl_xor_sync(~0u, lsum, o);
    if ((tid & 31) == 0) red[tid >> 5] = lsum;
    __syncthreads();
    float gsum = 0.f;
    #pragma unroll
    for (int w = 0; w < 8; ++w) gsum += red[w];
    float inv = 1.f / gsum;

    uint4 o4;
    *(__half2*)&o4.x = __halves2half2(__float2half_rn(e[0] * inv),
                                      __float2half_rn(e[1] * inv));
    *(__half2*)&o4.y = __halves2half2(__float2half_rn(e[2] * inv),
                                      __float2half_rn(e[3] * inv));
    *(__half2*)&o4.z = __halves2half2(__float2half_rn(e[4] * inv),
                                      __float2half_rn(e[5] * inv));
    *(__half2*)&o4.w = __halves2half2(__float2half_rn(e[6] * inv),
                                      __float2half_rn(e[7] * inv));
    ((uint4*)(ph + (size_t)blockIdx.x * S_LEN))[tid] = o4;
}

// ---------------------------------------------------------------------------
extern "C" void kernel_launch(void* const* d_in, const int* in_sizes, int n_in,
                              void* d_out, int out_size) {
    const float* x  = (const float*)d_in[0];
    const float* Wq = (const float*)d_in[1];
    const float* bq = (const float*)d_in[2];
    const float* Wk = (const float*)d_in[3];
    const float* bk = (const float*)d_in[4];
    const float* Wv = (const float*)d_in[5];
    const float* bv = (const float*)d_in[6];
    float* out = (float*)d_out;

    cudaFuncSetAttribute(gemm_fp16<0>, cudaFuncAttributeMaxDynamicSharedMemorySize,
                         GEMM_SMEM);
    cudaFuncSetAttribute(gemm_fp16<1>, cudaFuncAttributeMaxDynamicSharedMemorySize,
                         GEMM_SMEM);

    __half *xh, *wqh, *wkh, *wvh, *qh, *kh, *vh, *sch, *ph;
    cudaGetSymbolAddress((void**)&xh, g_xh);
    cudaGetSymbolAddress((void**)&wqh, g_wqh);
    cudaGetSymbolAddress((void**)&wkh, g_wkh);
    cudaGetSymbolAddress((void**)&wvh, g_wvh);
    cudaGetSymbolAddress((void**)&qh, g_qh);
    cudaGetSymbolAddress((void**)&kh, g_kh);
    cudaGetSymbolAddress((void**)&vh, g_vh);
    cudaGetSymbolAddress((void**)&sch, g_sch);
    cudaGetSymbolAddress((void**)&ph, g_ph);

    // 1) input conversions
    conv_x<<<MQKV, 256>>>(x, xh);
    {
        C3 c{};
        c.X[0] = Wq; c.X[1] = Wk; c.X[2] = Wv;
        c.H[0] = wqh; c.H[1] = wkh; c.H[2] = wvh;
        dim3 grid(DIM * DIM / 4 / 256, 1, 3);
        conv_hi3<<<grid, 256>>>(c, DIM * DIM / 4);
    }

    // 2) fused QKV projections (NT; one launch, z selects weight set)
    {
        G3 a{};
        a.Bh[0] = wqh; a.Bh[1] = wkh; a.Bh[2] = wvh;
        a.bias[0] = bq; a.bias[1] = bk; a.bias[2] = bv;
        a.Ch[0] = qh; a.Ch[1] = kh; a.Ch[2] = vh;
        dim3 grid(DIM / 128, MQKV / 128, 3);
        gemm_fp16<0><<<grid, 128, GEMM_SMEM>>>(xh, a,
                                               MQKV, DIM, DIM, 1.f, 0, 0, 0, 1);
    }

    // 3) scores = Q K^T / sqrt(D)  (NT) -> fp16 (halves score traffic)
    {
        G3 a{};
        a.Bh[0] = kh; a.Ch[0] = sch;
        dim3 grid(S_LEN / 128, S_LEN / 128, BATCH);
        gemm_fp16<0><<<grid, 128, GEMM_SMEM>>>(qh, a,
                                               S_LEN, S_LEN, DIM, 0.03125f,
                                               (size_t)S_LEN * DIM, (size_t)S_LEN * DIM,
                                               (size_t)S_LEN * S_LEN, 0);
    }

    // 4) softmax (fp16 in, fp16 out; FMA-pipe exp)
    softmax_h<<<BATCH * S_LEN, 256>>>(sch, ph);

    // 5) out = P V  (NN via ldmatrix.trans; V used in natural [S,D] layout)
    {
        G3 a{};
        a.Bh[0] = vh; a.Cf[0] = out;
        dim3 grid(DIM / 128, S_LEN / 128, BATCH);
        gemm_fp16<1><<<grid, 128, GEMM_SMEM>>>(ph, a,
                                               S_LEN, DIM, S_LEN, 1.f,
                                               (size_t)S_LEN * S_LEN, (size_t)S_LEN * DIM,
                                               (size_t)S_LEN * DIM, 0);
    }
}